// round 14
// baseline (speedup 1.0000x reference)
#include <cuda_runtime.h>
#include <cuda_fp16.h>
#include <cstdint>

#define M_TOTAL 32768      // B*N
#define D_EMB   768
#define VOCAB   4096
#define HID     128
#define KH      256

// ---------------- scratch globals (no cudaMalloc allowed) -------------------
__device__ __align__(16) __half g_Hh[(size_t)M_TOTAL * KH];
__device__ __align__(16) __half g_Hl[(size_t)M_TOTAL * KH];
__device__ __align__(16) __half g_WhT[(size_t)D_EMB * KH];   // [n][k]
__device__ __align__(16) __half g_WlT[(size_t)D_EMB * KH];
__device__ float g_bias[D_EMB];
__device__ __align__(16) __half g_Xh[(size_t)M_TOTAL * D_EMB];
__device__ __align__(16) __half g_Ch[(size_t)VOCAB * D_EMB];
__device__ __align__(16) float g_X[(size_t)M_TOTAL * D_EMB];
__device__ float g_csq[VOCAB];
// per-(row, vocab-chunk) candidate lists (8 chunks x CAP=8, padded with +inf)
__device__ float g_cand_d[(size_t)M_TOTAL * 64];
__device__ unsigned short g_cand_i[(size_t)M_TOTAL * 64];

// ---------------- mma.sync helpers ------------------------------------------
__device__ __forceinline__ uint32_t smem_to_u32(const void* p) {
    uint32_t a;
    asm("{ .reg .u64 t; cvta.to.shared.u64 t, %1; cvt.u32.u64 %0, t; }" : "=r"(a) : "l"(p));
    return a;
}
__device__ __forceinline__ void ldsm4(uint32_t* r, uint32_t addr) {
    asm volatile("ldmatrix.sync.aligned.m8n8.x4.shared.b16 {%0,%1,%2,%3}, [%4];"
        : "=r"(r[0]), "=r"(r[1]), "=r"(r[2]), "=r"(r[3]) : "r"(addr));
}
__device__ __forceinline__ void mma16816(float* c, const uint32_t* a, const uint32_t* b) {
    asm volatile("mma.sync.aligned.m16n8k16.row.col.f32.f16.f16.f32 "
        "{%0,%1,%2,%3}, {%4,%5,%6,%7}, {%8,%9}, {%0,%1,%2,%3};"
        : "+f"(c[0]), "+f"(c[1]), "+f"(c[2]), "+f"(c[3])
        : "r"(a[0]), "r"(a[1]), "r"(a[2]), "r"(a[3]), "r"(b[0]), "r"(b[1]));
}
__device__ __forceinline__ void cp_async16(uint32_t dst, const void* src) {
    asm volatile("cp.async.cg.shared.global [%0], [%1], 16;" :: "r"(dst), "l"(src) : "memory");
}
#define CP_COMMIT() asm volatile("cp.async.commit_group;" ::: "memory")
#define CP_WAIT0()  asm volatile("cp.async.wait_group 0;" ::: "memory")

__device__ __forceinline__ uint32_t sw_addr(uint32_t base, int row, int ch) {
    return base + row * 128 + ((ch ^ (row & 7)) << 4);
}
__device__ __forceinline__ void frag_ld(uint32_t* r, uint32_t tbase, int row0, int ch0, int lane) {
    int g = lane >> 3;
    int row = row0 + ((g & 1) << 3) + (lane & 7);
    int ch = ch0 + (g >> 1);
    ldsm4(r, sw_addr(tbase, row, ch));
}

// ---------------------------------------------------------------------------
// Fused prep kernel (R11 config)
// ---------------------------------------------------------------------------
#define PREP_CSQ0    0
#define PREP_CB0     512
#define PREP_W0      3584
#define PREP_HID0    4352
#define PREP_BLOCKS  (PREP_HID0 + (M_TOTAL / 16))

__global__ void prep_kernel(const float* __restrict__ coords,
                            const float* __restrict__ feats,
                            const float* __restrict__ Ws1, const float* __restrict__ bs1,
                            const float* __restrict__ Wf1, const float* __restrict__ bf1,
                            const float* __restrict__ Ws2, const float* __restrict__ Wf2,
                            const float* __restrict__ bs2, const float* __restrict__ bf2,
                            const float* __restrict__ cb) {
    int b = blockIdx.x;
    int tid = threadIdx.x;
    if (b >= PREP_HID0) {
        int m_base = (b - PREP_HID0) * 16;
        int j = tid;
        if (j < HID) {
            float w0 = Ws1[j], w1 = Ws1[HID + j], bb = bs1[j];
#pragma unroll
            for (int r = 0; r < 16; r++) {
                int m = m_base + r;
                float acc = fmaxf(bb + coords[m * 2] * w0 + coords[m * 2 + 1] * w1, 0.f);
                __half h = __float2half_rn(acc);
                g_Hh[m * KH + j] = h;
                g_Hl[m * KH + j] = __float2half_rn(acc - __half2float(h));
            }
        } else {
            int jj = j - HID;
            float wf[10];
#pragma unroll
            for (int i = 0; i < 10; i++) wf[i] = Wf1[i * HID + jj];
            float bb = bf1[jj];
#pragma unroll
            for (int r = 0; r < 16; r++) {
                int m = m_base + r;
                float acc = bb;
#pragma unroll
                for (int i = 0; i < 10; i++) acc += feats[m * 10 + i] * wf[i];
                acc = fmaxf(acc, 0.f);
                __half h = __float2half_rn(acc);
                g_Hh[m * KH + j] = h;
                g_Hl[m * KH + j] = __float2half_rn(acc - __half2float(h));
            }
        }
    } else if (b >= PREP_W0) {
        int t = (b - PREP_W0) * 256 + tid;
        if (t < D_EMB) g_bias[t] = bs2[t] + bf2[t];
        int kg = t / D_EMB, n = t - kg * D_EMB;
        float w = (kg < HID) ? Ws2[(size_t)kg * D_EMB + n] : Wf2[(size_t)(kg - HID) * D_EMB + n];
        __half h = __float2half_rn(w);
        __half l = __float2half_rn(w - __half2float(h));
        g_WhT[(size_t)n * KH + kg] = h;
        g_WlT[(size_t)n * KH + kg] = l;
    } else if (b >= PREP_CB0) {
        int i = (b - PREP_CB0) * 256 + tid;
        float4 v = ((const float4*)cb)[i];
        ((__half2*)g_Ch)[i * 2 + 0] = __halves2half2(__float2half_rn(v.x), __float2half_rn(v.y));
        ((__half2*)g_Ch)[i * 2 + 1] = __halves2half2(__float2half_rn(v.z), __float2half_rn(v.w));
    } else {
        int w = b * 8 + (tid >> 5);
        int lane = tid & 31;
        const float* row = cb + (size_t)w * D_EMB;
        float s = 0.f;
        for (int i = lane; i < D_EMB; i += 32) { float v = row[i]; s += v * v; }
#pragma unroll
        for (int o = 16; o; o >>= 1) s += __shfl_down_sync(0xffffffffu, s, o);
        if (lane == 0) g_csq[w] = s;
    }
}

// ---------------------------------------------------------------------------
// Kernel 3: embed GEMM via HMMA 3-term split. EM=64, occ 2 (R11 config)
// ---------------------------------------------------------------------------
#define EM 64
#define E_AH 0
#define E_AL 8192
#define E_BH 16384
#define E_BL 32768
#define ESTG_SZ 49152
#define E_SMEM (2 * ESTG_SZ)       // 98304

__device__ __forceinline__ void fill_e(uint32_t sbase, int m0, int n0, int kc, int tid) {
#pragma unroll
    for (int it = 0; it < 12; it++) {
        int t = it * 256 + tid;
        int c = t & 7;
        const __half* src;
        uint32_t dst;
        if (t < 512)       { int row = t >> 3;          src = g_Hh + (size_t)(m0 + row) * KH + kc + c * 8;  dst = sw_addr(sbase + E_AH, row, c); }
        else if (t < 1024) { int row = (t - 512) >> 3;  src = g_Hl + (size_t)(m0 + row) * KH + kc + c * 8;  dst = sw_addr(sbase + E_AL, row, c); }
        else if (t < 2048) { int row = (t - 1024) >> 3; src = g_WhT + (size_t)(n0 + row) * KH + kc + c * 8; dst = sw_addr(sbase + E_BH, row, c); }
        else               { int row = (t - 2048) >> 3; src = g_WlT + (size_t)(n0 + row) * KH + kc + c * 8; dst = sw_addr(sbase + E_BL, row, c); }
        cp_async16(dst, src);
    }
}

__global__ __launch_bounds__(256, 2) void embed_hmma_kernel() {
    extern __shared__ char sm[];
    uint32_t smu = smem_to_u32(sm);
    int tid = threadIdx.x;
    int lane = tid & 31, wid = tid >> 5;
    int n0 = blockIdx.x * 128;
    int m0 = blockIdx.y * EM;
    int wm = (wid & 1) * 32;
    int wn = (wid >> 1) * 32;
    int q = lane >> 2, p = lane & 3;

    fill_e(smu, m0, n0, 0, tid);
    CP_COMMIT();
    CP_WAIT0();
    __syncthreads();

    float acc[2][4][4];
#pragma unroll
    for (int mi = 0; mi < 2; mi++)
#pragma unroll
        for (int nj = 0; nj < 4; nj++)
#pragma unroll
            for (int e = 0; e < 4; e++) acc[mi][nj][e] = 0.f;

    for (int kt = 0; kt < 4; kt++) {
        if (kt + 1 < 4)
            fill_e(smu + ((kt + 1) & 1) * ESTG_SZ, m0, n0, (kt + 1) * 64, tid);
        CP_COMMIT();

        uint32_t sb = smu + (kt & 1) * ESTG_SZ;
#pragma unroll
        for (int ks = 0; ks < 4; ks++) {
            int ch0 = ks * 2;
            uint32_t ah[2][4], al[2][4], bh[2][4], bl[2][4];
#pragma unroll
            for (int mi = 0; mi < 2; mi++) {
                frag_ld(ah[mi], sb + E_AH, wm + mi * 16, ch0, lane);
                frag_ld(al[mi], sb + E_AL, wm + mi * 16, ch0, lane);
            }
#pragma unroll
            for (int nj = 0; nj < 2; nj++) {
                frag_ld(bh[nj], sb + E_BH, wn + nj * 16, ch0, lane);
                frag_ld(bl[nj], sb + E_BL, wn + nj * 16, ch0, lane);
            }
#pragma unroll
            for (int mi = 0; mi < 2; mi++)
#pragma unroll
                for (int nj = 0; nj < 2; nj++)
#pragma unroll
                    for (int h = 0; h < 2; h++) {
                        uint32_t bhf[2] = { bh[nj][h], bh[nj][h + 2] };
                        uint32_t blf[2] = { bl[nj][h], bl[nj][h + 2] };
                        float* c = acc[mi][nj * 2 + h];
                        mma16816(c, ah[mi], bhf);
                        mma16816(c, ah[mi], blf);
                        mma16816(c, al[mi], bhf);
                    }
        }
        CP_WAIT0();
        __syncthreads();
    }

#pragma unroll
    for (int mi = 0; mi < 2; mi++)
#pragma unroll
        for (int nj = 0; nj < 2; nj++)
#pragma unroll
            for (int h = 0; h < 2; h++) {
                const float* c = acc[mi][nj * 2 + h];
                int cn = n0 + wn + nj * 16 + h * 8 + p * 2;
                float bb0 = g_bias[cn], bb1 = g_bias[cn + 1];
                int r0 = m0 + wm + mi * 16 + q;
                float x00 = c[0] + bb0, x01 = c[1] + bb1;
                float x10 = c[2] + bb0, x11 = c[3] + bb1;
                size_t o0 = (size_t)r0 * D_EMB + cn;
                size_t o1 = (size_t)(r0 + 8) * D_EMB + cn;
                *(float2*)(g_X + o0) = make_float2(x00, x01);
                *(float2*)(g_X + o1) = make_float2(x10, x11);
                *(__half2*)(g_Xh + o0) = __halves2half2(__float2half_rn(x00), __float2half_rn(x01));
                *(__half2*)(g_Xh + o1) = __halves2half2(__float2half_rn(x10), __float2half_rn(x11));
            }
}

// ---------------------------------------------------------------------------
// Kernel 4 (pass 1): approx VQ, vocab-chunked (R13 config). Pads unused
// candidate slots with +inf so refine can merge lane-parallel.
// ---------------------------------------------------------------------------
#define VBM 128
#define VBN 128
#define VBK 64
#define NKT (D_EMB / VBK)         // 12
#define VCHUNK 512
#define NVT_U (VCHUNK / VBN)      // 4
#define NTILE_U (NVT_U * NKT)     // 48
#define MARGIN 0.5f
#define CAP 8

#define SOFF_CSQ 0                // 2KB
#define SOFF_TILES 2048
#define ARR_SZ 16384
#define STG_SZ (2 * ARR_SZ)
#define VQ_SMEM (SOFF_TILES + 2 * STG_SZ)   // 67584

__device__ __forceinline__ void fill_stage(uint32_t sbase, int m0, int v0, int kc, int tid) {
#pragma unroll
    for (int it = 0; it < 8; it++) {
        int t = it * 256 + tid;
        int arr = t >> 10;
        int idx = t & 1023;
        int row = idx >> 3, c = idx & 7;
        const __half* src = (arr == 0)
            ? g_Xh + (size_t)(m0 + row) * D_EMB + kc + c * 8
            : g_Ch + (size_t)(v0 + row) * D_EMB + kc + c * 8;
        cp_async16(sw_addr(sbase + arr * ARR_SZ, row, c), src);
    }
}

__global__ __launch_bounds__(256, 2) void vq_pass1_kernel() {
    extern __shared__ char sm[];
    uint32_t smu = smem_to_u32(sm);
    int tid = threadIdx.x;
    int lane = tid & 31, wid = tid >> 5;
    int m0 = (blockIdx.x >> 3) * VBM;
    int chunk = blockIdx.x & 7;
    int vb = chunk * VCHUNK;
    int wm = (wid & 3) * 32;
    int wn = (wid >> 2) * 64;
    int wnid = wid >> 2;
    int q = lane >> 2, p = lane & 3;

    if (tid < VCHUNK / 4)
        ((float4*)(sm + SOFF_CSQ))[tid] = ((const float4*)(g_csq + vb))[tid];

    fill_stage(smu + SOFF_TILES, m0, vb, 0, tid);
    CP_COMMIT();
    CP_WAIT0();
    __syncthreads();

    float v0a[4], v1a[4]; int i0a[4], i1a[4];
#pragma unroll
    for (int i = 0; i < 4; i++) { v0a[i] = 3.4e38f; v1a[i] = 3.4e38f; i0a[i] = 0; i1a[i] = 0; }

    const float* scq = (const float*)(sm + SOFF_CSQ);

    for (int vt = 0; vt < NVT_U; vt++) {
        float acc[2][8][4];
#pragma unroll
        for (int mi = 0; mi < 2; mi++)
#pragma unroll
            for (int nj = 0; nj < 8; nj++)
#pragma unroll
                for (int e = 0; e < 4; e++) acc[mi][nj][e] = 0.f;

        for (int kt = 0; kt < NKT; kt++) {
            int g = vt * NKT + kt;
            int ng = g + 1;
            if (ng < NTILE_U) {
                int nvt = ng / NKT, nkt = ng - nvt * NKT;
                fill_stage(smu + SOFF_TILES + (ng & 1) * STG_SZ, m0, vb + nvt * VBN, nkt * VBK, tid);
            }
            CP_COMMIT();

            uint32_t sb = smu + SOFF_TILES + (g & 1) * STG_SZ;
            uint32_t AH = sb, BH = sb + ARR_SZ;
#pragma unroll
            for (int ks = 0; ks < 4; ks++) {
                int ch0 = ks * 2;
                uint32_t ah[2][4], bh[4][4];
#pragma unroll
                for (int mi = 0; mi < 2; mi++) frag_ld(ah[mi], AH, wm + mi * 16, ch0, lane);
#pragma unroll
                for (int nj = 0; nj < 4; nj++) frag_ld(bh[nj], BH, wn + nj * 16, ch0, lane);
#pragma unroll
                for (int mi = 0; mi < 2; mi++)
#pragma unroll
                    for (int nj = 0; nj < 4; nj++)
#pragma unroll
                        for (int h = 0; h < 2; h++) {
                            uint32_t bf[2] = { bh[nj][h], bh[nj][h + 2] };
                            mma16816(acc[mi][nj * 2 + h], ah[mi], bf);
                        }
            }
            CP_WAIT0();
            __syncthreads();
        }

#pragma unroll
        for (int mi = 0; mi < 2; mi++)
#pragma unroll
            for (int nj = 0; nj < 4; nj++)
#pragma unroll
                for (int h = 0; h < 2; h++) {
                    int nl = vt * VBN + wn + nj * 16 + h * 8 + p * 2;
                    const float* c = acc[mi][nj * 2 + h];
                    float cs0 = scq[nl], cs1 = scq[nl + 1];
#pragma unroll
                    for (int e = 0; e < 4; e++) {
                        int s = mi * 2 + (e >> 1);
                        int nn = vb + nl + (e & 1);
                        float d = fmaf(-2.f, c[e], (e & 1) ? cs1 : cs0);
                        if (d < v1a[s]) {
                            if (d < v0a[s]) { v1a[s] = v0a[s]; i1a[s] = i0a[s]; v0a[s] = d; i0a[s] = nn; }
                            else            { v1a[s] = d; i1a[s] = nn; }
                        }
                    }
                }
    }

    // dump best-2 sets, filter vs chunk best, write CAP-padded global lists
    __syncthreads();
    float* s_cval = (float*)(sm + SOFF_TILES);                          // [128][16]
    unsigned short* s_cidx = (unsigned short*)(sm + SOFF_TILES + 8192); // [128][16]
    int bslot = (wnid * 4 + p) * 2;
#pragma unroll
    for (int s = 0; s < 4; s++) {
        int row = wm + ((s >> 1) << 4) + ((s & 1) << 3) + q;
        s_cval[row * 16 + bslot] = v0a[s];
        s_cidx[row * 16 + bslot] = (unsigned short)i0a[s];
        s_cval[row * 16 + bslot + 1] = v1a[s];
        s_cidx[row * 16 + bslot + 1] = (unsigned short)i1a[s];
    }
    __syncthreads();
    if (tid < VBM) {
        int row = tid;
        int grow = m0 + row;
        float best = s_cval[row * 16]; int bj = 0;
#pragma unroll
        for (int j = 1; j < 16; j++) {
            float v = s_cval[row * 16 + j];
            if (v < best) { best = v; bj = j; }
        }
        size_t base = (size_t)grow * 64 + chunk * CAP;
        float dbuf[CAP]; unsigned short ibuf[CAP];
        dbuf[0] = best; ibuf[0] = s_cidx[row * 16 + bj];
        int cnt = 1;
#pragma unroll
        for (int j = 0; j < 16; j++) {
            if (j == bj) continue;
            float v = s_cval[row * 16 + j];
            if (v < best + MARGIN && cnt < CAP) {
                dbuf[cnt] = v; ibuf[cnt] = s_cidx[row * 16 + j]; cnt++;
            }
        }
#pragma unroll
        for (int j = 0; j < CAP; j++) {
            g_cand_d[base + j] = (j < cnt) ? dbuf[j] : 3.4e38f;
            g_cand_i[base + j] = (j < cnt) ? ibuf[j] : 0;
        }
    }
}

// ---------------------------------------------------------------------------
// Kernel 5 (pass 2): lane-parallel merge + exact fp32 refine; tokens+gather
// ---------------------------------------------------------------------------
__global__ __launch_bounds__(256) void vq_refine_kernel(const float* __restrict__ cb,
                                                        float* __restrict__ out_tok,
                                                        float* __restrict__ out_q) {
    int lane = threadIdx.x & 31, wid = threadIdx.x >> 5;
    int row = blockIdx.x * 8 + wid;

    float x[24];
#pragma unroll
    for (int j = 0; j < 24; j++) x[j] = g_X[(size_t)row * D_EMB + j * 32 + lane];

    // lane-parallel merge: 64 padded entries, 2 per lane
    size_t cb64 = (size_t)row * 64;
    float d0 = g_cand_d[cb64 + lane];
    float d1 = g_cand_d[cb64 + 32 + lane];
    float m = fminf(d0, d1);
#pragma unroll
    for (int o = 16; o; o >>= 1) m = fminf(m, __shfl_xor_sync(0xffffffffu, m, o));
    float thr = m + MARGIN;
    unsigned mask0 = __ballot_sync(0xffffffffu, d0 < thr);
    unsigned mask1 = __ballot_sync(0xffffffffu, d1 < thr);

    float best = 3.4e38f; int bi = VOCAB;
#pragma unroll 1
    for (int half = 0; half < 2; half++) {
        unsigned mm = half ? mask1 : mask0;
        int off = half ? 32 : 0;
        while (mm) {
            int b = __ffs(mm) - 1;
            mm &= mm - 1;
            int c = g_cand_i[cb64 + off + b];
            const float* crow = cb + (size_t)c * D_EMB;
            float dot = 0.f;
#pragma unroll
            for (int j = 0; j < 24; j++) dot = fmaf(x[j], crow[j * 32 + lane], dot);
#pragma unroll
            for (int o = 16; o; o >>= 1) dot += __shfl_xor_sync(0xffffffffu, dot, o);
            float d = g_csq[c] - 2.f * dot;
            if (d < best || (d == best && c < bi)) { best = d; bi = c; }
        }
    }
    if (lane == 0) out_tok[row] = (float)bi;
    const float4* src = (const float4*)(cb + (size_t)bi * D_EMB);
    float4* dst = (float4*)(out_q + (size_t)row * D_EMB);
#pragma unroll
    for (int j = 0; j < 6; j++) dst[lane + j * 32] = src[lane + j * 32];
}

// ---------------------------------------------------------------------------
extern "C" void kernel_launch(void* const* d_in, const int* in_sizes, int n_in,
                              void* d_out, int out_size) {
    const float* coords = (const float*)d_in[0];
    const float* feats  = (const float*)d_in[1];
    const float* Ws1 = (const float*)d_in[2];
    const float* bs1 = (const float*)d_in[3];
    const float* Ws2 = (const float*)d_in[4];
    const float* bs2 = (const float*)d_in[5];
    const float* Wf1 = (const float*)d_in[6];
    const float* bf1 = (const float*)d_in[7];
    const float* Wf2 = (const float*)d_in[8];
    const float* bf2 = (const float*)d_in[9];
    const float* cb  = (const float*)d_in[10];

    float* outf    = (float*)d_out;
    float* out_tok = outf;               // tokens [32768] as float
    float* out_q   = outf + M_TOTAL;     // quantized [32768, 768]

    static bool attr_set = false;
    if (!attr_set) {
        cudaFuncSetAttribute(vq_pass1_kernel, cudaFuncAttributeMaxDynamicSharedMemorySize, VQ_SMEM);
        cudaFuncSetAttribute(embed_hmma_kernel, cudaFuncAttributeMaxDynamicSharedMemorySize, E_SMEM);
        attr_set = true;
    }

    prep_kernel<<<PREP_BLOCKS, 256>>>(coords, feats, Ws1, bs1, Wf1, bf1,
                                      Ws2, Wf2, bs2, bf2, cb);
    dim3 g2(D_EMB / 128, M_TOTAL / EM);    // n fastest, m slow
    embed_hmma_kernel<<<g2, 256, E_SMEM>>>();
    vq_pass1_kernel<<<(M_TOTAL / VBM) * 8, 256, VQ_SMEM>>>();
    vq_refine_kernel<<<M_TOTAL / 8, 256>>>(cb, out_tok, out_q);
}

// round 15
// speedup vs baseline: 1.0482x; 1.0482x over previous
#include <cuda_runtime.h>
#include <cuda_fp16.h>
#include <cstdint>

#define M_TOTAL 32768      // B*N
#define D_EMB   768
#define VOCAB   4096
#define HID     128
#define KH      256

// ---------------- scratch globals (no cudaMalloc allowed) -------------------
__device__ __align__(16) __half g_Hh[(size_t)M_TOTAL * KH];
__device__ __align__(16) __half g_Hl[(size_t)M_TOTAL * KH];
__device__ __align__(16) __half g_WhT[(size_t)D_EMB * KH];   // [n][k]
__device__ __align__(16) __half g_WlT[(size_t)D_EMB * KH];
__device__ float g_bias[D_EMB];
__device__ __align__(16) __half g_Xh[(size_t)M_TOTAL * D_EMB];
__device__ __align__(16) __half g_Ch[(size_t)VOCAB * D_EMB];
__device__ __align__(16) float g_X[(size_t)M_TOTAL * D_EMB];
__device__ float g_csq[VOCAB];
// per-(row, vocab-chunk) candidate lists (8 chunks x CAP=8, sparse + counts)
__device__ float g_cand_d[(size_t)M_TOTAL * 64];
__device__ unsigned short g_cand_i[(size_t)M_TOTAL * 64];
__device__ int g_cand_n[(size_t)M_TOTAL * 8];

// ---------------- mma.sync helpers ------------------------------------------
__device__ __forceinline__ uint32_t smem_to_u32(const void* p) {
    uint32_t a;
    asm("{ .reg .u64 t; cvta.to.shared.u64 t, %1; cvt.u32.u64 %0, t; }" : "=r"(a) : "l"(p));
    return a;
}
__device__ __forceinline__ void ldsm4(uint32_t* r, uint32_t addr) {
    asm volatile("ldmatrix.sync.aligned.m8n8.x4.shared.b16 {%0,%1,%2,%3}, [%4];"
        : "=r"(r[0]), "=r"(r[1]), "=r"(r[2]), "=r"(r[3]) : "r"(addr));
}
__device__ __forceinline__ void mma16816(float* c, const uint32_t* a, const uint32_t* b) {
    asm volatile("mma.sync.aligned.m16n8k16.row.col.f32.f16.f16.f32 "
        "{%0,%1,%2,%3}, {%4,%5,%6,%7}, {%8,%9}, {%0,%1,%2,%3};"
        : "+f"(c[0]), "+f"(c[1]), "+f"(c[2]), "+f"(c[3])
        : "r"(a[0]), "r"(a[1]), "r"(a[2]), "r"(a[3]), "r"(b[0]), "r"(b[1]));
}
__device__ __forceinline__ void cp_async16(uint32_t dst, const void* src) {
    asm volatile("cp.async.cg.shared.global [%0], [%1], 16;" :: "r"(dst), "l"(src) : "memory");
}
#define CP_COMMIT() asm volatile("cp.async.commit_group;" ::: "memory")
#define CP_WAIT0()  asm volatile("cp.async.wait_group 0;" ::: "memory")

__device__ __forceinline__ uint32_t sw_addr(uint32_t base, int row, int ch) {
    return base + row * 128 + ((ch ^ (row & 7)) << 4);
}
__device__ __forceinline__ void frag_ld(uint32_t* r, uint32_t tbase, int row0, int ch0, int lane) {
    int g = lane >> 3;
    int row = row0 + ((g & 1) << 3) + (lane & 7);
    int ch = ch0 + (g >> 1);
    ldsm4(r, sw_addr(tbase, row, ch));
}

// ---------------------------------------------------------------------------
// Fused prep kernel (R11 config)
// ---------------------------------------------------------------------------
#define PREP_CSQ0    0
#define PREP_CB0     512
#define PREP_W0      3584
#define PREP_HID0    4352
#define PREP_BLOCKS  (PREP_HID0 + (M_TOTAL / 16))

__global__ void prep_kernel(const float* __restrict__ coords,
                            const float* __restrict__ feats,
                            const float* __restrict__ Ws1, const float* __restrict__ bs1,
                            const float* __restrict__ Wf1, const float* __restrict__ bf1,
                            const float* __restrict__ Ws2, const float* __restrict__ Wf2,
                            const float* __restrict__ bs2, const float* __restrict__ bf2,
                            const float* __restrict__ cb) {
    int b = blockIdx.x;
    int tid = threadIdx.x;
    if (b >= PREP_HID0) {
        int m_base = (b - PREP_HID0) * 16;
        int j = tid;
        if (j < HID) {
            float w0 = Ws1[j], w1 = Ws1[HID + j], bb = bs1[j];
#pragma unroll
            for (int r = 0; r < 16; r++) {
                int m = m_base + r;
                float acc = fmaxf(bb + coords[m * 2] * w0 + coords[m * 2 + 1] * w1, 0.f);
                __half h = __float2half_rn(acc);
                g_Hh[m * KH + j] = h;
                g_Hl[m * KH + j] = __float2half_rn(acc - __half2float(h));
            }
        } else {
            int jj = j - HID;
            float wf[10];
#pragma unroll
            for (int i = 0; i < 10; i++) wf[i] = Wf1[i * HID + jj];
            float bb = bf1[jj];
#pragma unroll
            for (int r = 0; r < 16; r++) {
                int m = m_base + r;
                float acc = bb;
#pragma unroll
                for (int i = 0; i < 10; i++) acc += feats[m * 10 + i] * wf[i];
                acc = fmaxf(acc, 0.f);
                __half h = __float2half_rn(acc);
                g_Hh[m * KH + j] = h;
                g_Hl[m * KH + j] = __float2half_rn(acc - __half2float(h));
            }
        }
    } else if (b >= PREP_W0) {
        int t = (b - PREP_W0) * 256 + tid;
        if (t < D_EMB) g_bias[t] = bs2[t] + bf2[t];
        int kg = t / D_EMB, n = t - kg * D_EMB;
        float w = (kg < HID) ? Ws2[(size_t)kg * D_EMB + n] : Wf2[(size_t)(kg - HID) * D_EMB + n];
        __half h = __float2half_rn(w);
        __half l = __float2half_rn(w - __half2float(h));
        g_WhT[(size_t)n * KH + kg] = h;
        g_WlT[(size_t)n * KH + kg] = l;
    } else if (b >= PREP_CB0) {
        int i = (b - PREP_CB0) * 256 + tid;
        float4 v = ((const float4*)cb)[i];
        ((__half2*)g_Ch)[i * 2 + 0] = __halves2half2(__float2half_rn(v.x), __float2half_rn(v.y));
        ((__half2*)g_Ch)[i * 2 + 1] = __halves2half2(__float2half_rn(v.z), __float2half_rn(v.w));
    } else {
        int w = b * 8 + (tid >> 5);
        int lane = tid & 31;
        const float* row = cb + (size_t)w * D_EMB;
        float s = 0.f;
        for (int i = lane; i < D_EMB; i += 32) { float v = row[i]; s += v * v; }
#pragma unroll
        for (int o = 16; o; o >>= 1) s += __shfl_down_sync(0xffffffffu, s, o);
        if (lane == 0) g_csq[w] = s;
    }
}

// ---------------------------------------------------------------------------
// Kernel 3: embed GEMM via HMMA 3-term split. EM=64, occ 2 (R11 config)
// ---------------------------------------------------------------------------
#define EM 64
#define E_AH 0
#define E_AL 8192
#define E_BH 16384
#define E_BL 32768
#define ESTG_SZ 49152
#define E_SMEM (2 * ESTG_SZ)       // 98304

__device__ __forceinline__ void fill_e(uint32_t sbase, int m0, int n0, int kc, int tid) {
#pragma unroll
    for (int it = 0; it < 12; it++) {
        int t = it * 256 + tid;
        int c = t & 7;
        const __half* src;
        uint32_t dst;
        if (t < 512)       { int row = t >> 3;          src = g_Hh + (size_t)(m0 + row) * KH + kc + c * 8;  dst = sw_addr(sbase + E_AH, row, c); }
        else if (t < 1024) { int row = (t - 512) >> 3;  src = g_Hl + (size_t)(m0 + row) * KH + kc + c * 8;  dst = sw_addr(sbase + E_AL, row, c); }
        else if (t < 2048) { int row = (t - 1024) >> 3; src = g_WhT + (size_t)(n0 + row) * KH + kc + c * 8; dst = sw_addr(sbase + E_BH, row, c); }
        else               { int row = (t - 2048) >> 3; src = g_WlT + (size_t)(n0 + row) * KH + kc + c * 8; dst = sw_addr(sbase + E_BL, row, c); }
        cp_async16(dst, src);
    }
}

__global__ __launch_bounds__(256, 2) void embed_hmma_kernel() {
    extern __shared__ char sm[];
    uint32_t smu = smem_to_u32(sm);
    int tid = threadIdx.x;
    int lane = tid & 31, wid = tid >> 5;
    int n0 = blockIdx.x * 128;
    int m0 = blockIdx.y * EM;
    int wm = (wid & 1) * 32;
    int wn = (wid >> 1) * 32;
    int q = lane >> 2, p = lane & 3;

    fill_e(smu, m0, n0, 0, tid);
    CP_COMMIT();
    CP_WAIT0();
    __syncthreads();

    float acc[2][4][4];
#pragma unroll
    for (int mi = 0; mi < 2; mi++)
#pragma unroll
        for (int nj = 0; nj < 4; nj++)
#pragma unroll
            for (int e = 0; e < 4; e++) acc[mi][nj][e] = 0.f;

    for (int kt = 0; kt < 4; kt++) {
        if (kt + 1 < 4)
            fill_e(smu + ((kt + 1) & 1) * ESTG_SZ, m0, n0, (kt + 1) * 64, tid);
        CP_COMMIT();

        uint32_t sb = smu + (kt & 1) * ESTG_SZ;
#pragma unroll
        for (int ks = 0; ks < 4; ks++) {
            int ch0 = ks * 2;
            uint32_t ah[2][4], al[2][4], bh[2][4], bl[2][4];
#pragma unroll
            for (int mi = 0; mi < 2; mi++) {
                frag_ld(ah[mi], sb + E_AH, wm + mi * 16, ch0, lane);
                frag_ld(al[mi], sb + E_AL, wm + mi * 16, ch0, lane);
            }
#pragma unroll
            for (int nj = 0; nj < 2; nj++) {
                frag_ld(bh[nj], sb + E_BH, wn + nj * 16, ch0, lane);
                frag_ld(bl[nj], sb + E_BL, wn + nj * 16, ch0, lane);
            }
#pragma unroll
            for (int mi = 0; mi < 2; mi++)
#pragma unroll
                for (int nj = 0; nj < 2; nj++)
#pragma unroll
                    for (int h = 0; h < 2; h++) {
                        uint32_t bhf[2] = { bh[nj][h], bh[nj][h + 2] };
                        uint32_t blf[2] = { bl[nj][h], bl[nj][h + 2] };
                        float* c = acc[mi][nj * 2 + h];
                        mma16816(c, ah[mi], bhf);
                        mma16816(c, ah[mi], blf);
                        mma16816(c, al[mi], bhf);
                    }
        }
        CP_WAIT0();
        __syncthreads();
    }

#pragma unroll
    for (int mi = 0; mi < 2; mi++)
#pragma unroll
        for (int nj = 0; nj < 2; nj++)
#pragma unroll
            for (int h = 0; h < 2; h++) {
                const float* c = acc[mi][nj * 2 + h];
                int cn = n0 + wn + nj * 16 + h * 8 + p * 2;
                float bb0 = g_bias[cn], bb1 = g_bias[cn + 1];
                int r0 = m0 + wm + mi * 16 + q;
                float x00 = c[0] + bb0, x01 = c[1] + bb1;
                float x10 = c[2] + bb0, x11 = c[3] + bb1;
                size_t o0 = (size_t)r0 * D_EMB + cn;
                size_t o1 = (size_t)(r0 + 8) * D_EMB + cn;
                *(float2*)(g_X + o0) = make_float2(x00, x01);
                *(float2*)(g_X + o1) = make_float2(x10, x11);
                *(__half2*)(g_Xh + o0) = __halves2half2(__float2half_rn(x00), __float2half_rn(x01));
                *(__half2*)(g_Xh + o1) = __halves2half2(__float2half_rn(x10), __float2half_rn(x11));
            }
}

// ---------------------------------------------------------------------------
// Kernel 4 (pass 1): approx VQ, vocab-chunked (R13 config, sparse cand write)
// ---------------------------------------------------------------------------
#define VBM 128
#define VBN 128
#define VBK 64
#define NKT (D_EMB / VBK)         // 12
#define VCHUNK 512
#define NVT_U (VCHUNK / VBN)      // 4
#define NTILE_U (NVT_U * NKT)     // 48
#define MARGIN 0.5f
#define CAP 8

#define SOFF_CSQ 0                // 2KB
#define SOFF_TILES 2048
#define ARR_SZ 16384
#define STG_SZ (2 * ARR_SZ)
#define VQ_SMEM (SOFF_TILES + 2 * STG_SZ)   // 67584

__device__ __forceinline__ void fill_stage(uint32_t sbase, int m0, int v0, int kc, int tid) {
#pragma unroll
    for (int it = 0; it < 8; it++) {
        int t = it * 256 + tid;
        int arr = t >> 10;
        int idx = t & 1023;
        int row = idx >> 3, c = idx & 7;
        const __half* src = (arr == 0)
            ? g_Xh + (size_t)(m0 + row) * D_EMB + kc + c * 8
            : g_Ch + (size_t)(v0 + row) * D_EMB + kc + c * 8;
        cp_async16(sw_addr(sbase + arr * ARR_SZ, row, c), src);
    }
}

__global__ __launch_bounds__(256, 2) void vq_pass1_kernel() {
    extern __shared__ char sm[];
    uint32_t smu = smem_to_u32(sm);
    int tid = threadIdx.x;
    int lane = tid & 31, wid = tid >> 5;
    int m0 = (blockIdx.x >> 3) * VBM;
    int chunk = blockIdx.x & 7;
    int vb = chunk * VCHUNK;
    int wm = (wid & 3) * 32;
    int wn = (wid >> 2) * 64;
    int wnid = wid >> 2;
    int q = lane >> 2, p = lane & 3;

    if (tid < VCHUNK / 4)
        ((float4*)(sm + SOFF_CSQ))[tid] = ((const float4*)(g_csq + vb))[tid];

    fill_stage(smu + SOFF_TILES, m0, vb, 0, tid);
    CP_COMMIT();
    CP_WAIT0();
    __syncthreads();

    float v0a[4], v1a[4]; int i0a[4], i1a[4];
#pragma unroll
    for (int i = 0; i < 4; i++) { v0a[i] = 3.4e38f; v1a[i] = 3.4e38f; i0a[i] = 0; i1a[i] = 0; }

    const float* scq = (const float*)(sm + SOFF_CSQ);

    for (int vt = 0; vt < NVT_U; vt++) {
        float acc[2][8][4];
#pragma unroll
        for (int mi = 0; mi < 2; mi++)
#pragma unroll
            for (int nj = 0; nj < 8; nj++)
#pragma unroll
                for (int e = 0; e < 4; e++) acc[mi][nj][e] = 0.f;

        for (int kt = 0; kt < NKT; kt++) {
            int g = vt * NKT + kt;
            int ng = g + 1;
            if (ng < NTILE_U) {
                int nvt = ng / NKT, nkt = ng - nvt * NKT;
                fill_stage(smu + SOFF_TILES + (ng & 1) * STG_SZ, m0, vb + nvt * VBN, nkt * VBK, tid);
            }
            CP_COMMIT();

            uint32_t sb = smu + SOFF_TILES + (g & 1) * STG_SZ;
            uint32_t AH = sb, BH = sb + ARR_SZ;
#pragma unroll
            for (int ks = 0; ks < 4; ks++) {
                int ch0 = ks * 2;
                uint32_t ah[2][4], bh[4][4];
#pragma unroll
                for (int mi = 0; mi < 2; mi++) frag_ld(ah[mi], AH, wm + mi * 16, ch0, lane);
#pragma unroll
                for (int nj = 0; nj < 4; nj++) frag_ld(bh[nj], BH, wn + nj * 16, ch0, lane);
#pragma unroll
                for (int mi = 0; mi < 2; mi++)
#pragma unroll
                    for (int nj = 0; nj < 4; nj++)
#pragma unroll
                        for (int h = 0; h < 2; h++) {
                            uint32_t bf[2] = { bh[nj][h], bh[nj][h + 2] };
                            mma16816(acc[mi][nj * 2 + h], ah[mi], bf);
                        }
            }
            CP_WAIT0();
            __syncthreads();
        }

#pragma unroll
        for (int mi = 0; mi < 2; mi++)
#pragma unroll
            for (int nj = 0; nj < 4; nj++)
#pragma unroll
                for (int h = 0; h < 2; h++) {
                    int nl = vt * VBN + wn + nj * 16 + h * 8 + p * 2;
                    const float* c = acc[mi][nj * 2 + h];
                    float cs0 = scq[nl], cs1 = scq[nl + 1];
#pragma unroll
                    for (int e = 0; e < 4; e++) {
                        int s = mi * 2 + (e >> 1);
                        int nn = vb + nl + (e & 1);
                        float d = fmaf(-2.f, c[e], (e & 1) ? cs1 : cs0);
                        if (d < v1a[s]) {
                            if (d < v0a[s]) { v1a[s] = v0a[s]; i1a[s] = i0a[s]; v0a[s] = d; i0a[s] = nn; }
                            else            { v1a[s] = d; i1a[s] = nn; }
                        }
                    }
                }
    }

    // dump best-2 sets, filter vs chunk best, write sparse lists + counts
    __syncthreads();
    float* s_cval = (float*)(sm + SOFF_TILES);                          // [128][16]
    unsigned short* s_cidx = (unsigned short*)(sm + SOFF_TILES + 8192); // [128][16]
    int bslot = (wnid * 4 + p) * 2;
#pragma unroll
    for (int s = 0; s < 4; s++) {
        int row = wm + ((s >> 1) << 4) + ((s & 1) << 3) + q;
        s_cval[row * 16 + bslot] = v0a[s];
        s_cidx[row * 16 + bslot] = (unsigned short)i0a[s];
        s_cval[row * 16 + bslot + 1] = v1a[s];
        s_cidx[row * 16 + bslot + 1] = (unsigned short)i1a[s];
    }
    __syncthreads();
    if (tid < VBM) {
        int row = tid;
        int grow = m0 + row;
        float best = s_cval[row * 16]; int bj = 0;
#pragma unroll
        for (int j = 1; j < 16; j++) {
            float v = s_cval[row * 16 + j];
            if (v < best) { best = v; bj = j; }
        }
        size_t base = (size_t)grow * 64 + chunk * CAP;
        int cnt = 0;
        g_cand_d[base] = best;
        g_cand_i[base] = s_cidx[row * 16 + bj];
        cnt = 1;
#pragma unroll
        for (int j = 0; j < 16; j++) {
            if (j == bj) continue;
            float v = s_cval[row * 16 + j];
            if (v < best + MARGIN && cnt < CAP) {
                g_cand_d[base + cnt] = v;
                g_cand_i[base + cnt] = s_cidx[row * 16 + j];
                cnt++;
            }
        }
        g_cand_n[(size_t)grow * 8 + chunk] = cnt;
    }
}

// ---------------------------------------------------------------------------
// Kernel 5 (pass 2): lane-parallel merge (cnt-masked) + exact refine
// ---------------------------------------------------------------------------
__global__ __launch_bounds__(256) void vq_refine_kernel(const float* __restrict__ cb,
                                                        float* __restrict__ out_tok,
                                                        float* __restrict__ out_q) {
    int lane = threadIdx.x & 31, wid = threadIdx.x >> 5;
    int row = blockIdx.x * 8 + wid;

    float x[24];
#pragma unroll
    for (int j = 0; j < 24; j++) x[j] = g_X[(size_t)row * D_EMB + j * 32 + lane];

    // lane-parallel merge: lane i covers entries i and i+32; validity by cnt
    size_t cb64 = (size_t)row * 64;
    int slot = lane & 7;
    int cnt0 = g_cand_n[(size_t)row * 8 + (lane >> 3)];
    int cnt1 = g_cand_n[(size_t)row * 8 + 4 + (lane >> 3)];
    float d0 = (slot < cnt0) ? g_cand_d[cb64 + lane] : 3.4e38f;
    float d1 = (slot < cnt1) ? g_cand_d[cb64 + 32 + lane] : 3.4e38f;
    float m = fminf(d0, d1);
#pragma unroll
    for (int o = 16; o; o >>= 1) m = fminf(m, __shfl_xor_sync(0xffffffffu, m, o));
    float thr = m + MARGIN;
    unsigned mask0 = __ballot_sync(0xffffffffu, d0 < thr);
    unsigned mask1 = __ballot_sync(0xffffffffu, d1 < thr);

    float best = 3.4e38f; int bi = VOCAB;
#pragma unroll 1
    for (int half = 0; half < 2; half++) {
        unsigned mm = half ? mask1 : mask0;
        int off = half ? 32 : 0;
        while (mm) {
            int b = __ffs(mm) - 1;
            mm &= mm - 1;
            int c = g_cand_i[cb64 + off + b];
            const float* crow = cb + (size_t)c * D_EMB;
            float dot = 0.f;
#pragma unroll
            for (int j = 0; j < 24; j++) dot = fmaf(x[j], crow[j * 32 + lane], dot);
#pragma unroll
            for (int o = 16; o; o >>= 1) dot += __shfl_xor_sync(0xffffffffu, dot, o);
            float d = g_csq[c] - 2.f * dot;
            if (d < best || (d == best && c < bi)) { best = d; bi = c; }
        }
    }
    if (lane == 0) out_tok[row] = (float)bi;
    const float4* src = (const float4*)(cb + (size_t)bi * D_EMB);
    float4* dst = (float4*)(out_q + (size_t)row * D_EMB);
#pragma unroll
    for (int j = 0; j < 6; j++) dst[lane + j * 32] = src[lane + j * 32];
}

// ---------------------------------------------------------------------------
extern "C" void kernel_launch(void* const* d_in, const int* in_sizes, int n_in,
                              void* d_out, int out_size) {
    const float* coords = (const float*)d_in[0];
    const float* feats  = (const float*)d_in[1];
    const float* Ws1 = (const float*)d_in[2];
    const float* bs1 = (const float*)d_in[3];
    const float* Ws2 = (const float*)d_in[4];
    const float* bs2 = (const float*)d_in[5];
    const float* Wf1 = (const float*)d_in[6];
    const float* bf1 = (const float*)d_in[7];
    const float* Wf2 = (const float*)d_in[8];
    const float* bf2 = (const float*)d_in[9];
    const float* cb  = (const float*)d_in[10];

    float* outf    = (float*)d_out;
    float* out_tok = outf;               // tokens [32768] as float
    float* out_q   = outf + M_TOTAL;     // quantized [32768, 768]

    static bool attr_set = false;
    if (!attr_set) {
        cudaFuncSetAttribute(vq_pass1_kernel, cudaFuncAttributeMaxDynamicSharedMemorySize, VQ_SMEM);
        cudaFuncSetAttribute(embed_hmma_kernel, cudaFuncAttributeMaxDynamicSharedMemorySize, E_SMEM);
        attr_set = true;
    }

    prep_kernel<<<PREP_BLOCKS, 256>>>(coords, feats, Ws1, bs1, Wf1, bf1,
                                      Ws2, Wf2, bs2, bf2, cb);
    dim3 g2(D_EMB / 128, M_TOTAL / EM);    // n fastest, m slow
    embed_hmma_kernel<<<g2, 256, E_SMEM>>>();
    vq_pass1_kernel<<<(M_TOTAL / VBM) * 8, 256, VQ_SMEM>>>();
    vq_refine_kernel<<<M_TOTAL / 8, 256>>>(cb, out_tok, out_q);
}